// round 13
// baseline (speedup 1.0000x reference)
#include <cuda_runtime.h>
#include <cuda_bf16.h>
#include <cuda_fp16.h>
#include <cstdint>
#include <string.h>
#include <math.h>

typedef __nv_bfloat16 bf16;

#define B_ 8
#define C_ 512
#define N_ 2048
#define CH_ 256

// ---- device-global scratch ----
__device__ bf16   g_xt [B_ * N_ * C_];             // [n][c] bf16
__device__ bf16   g_Wqk[2 * CH_ * C_];             // rows 0-255 Wq, 256-511 Wk
__device__ bf16   g_Wv [C_ * C_];
__device__ float  g_bqk[2 * CH_];                  // packed bq|bk
__device__ bf16   g_QK [B_ * N_ * C_];             // [n][0..255]=Q, [256..511]=K
__device__ __half g_V  [B_ * C_ * N_];             // [c][m] fp16
__device__ bf16   g_S  [(size_t)B_ * N_ * N_];     // [n][m] unscaled logits, bf16
__device__ __half g_P  [(size_t)B_ * N_ * N_];     // [n][m] probs, fp16

// ===========================================================================
// PTX helpers
// ===========================================================================
__device__ __forceinline__ uint32_t smem_u32(const void* p) {
    uint32_t a;
    asm("{ .reg .u64 t; cvta.to.shared.u64 t, %1; cvt.u32.u64 %0, t; }"
        : "=r"(a) : "l"(p));
    return a;
}
__device__ __forceinline__ void cp_async16(uint32_t dst, const void* src) {
    asm volatile("cp.async.cg.shared.global [%0], [%1], 16;\n" :: "r"(dst), "l"(src));
}
__device__ __forceinline__ void cp_commit() {
    asm volatile("cp.async.commit_group;\n");
}
template<int NW> __device__ __forceinline__ void cp_wait() {
    asm volatile("cp.async.wait_group %0;\n" :: "n"(NW));
}
__device__ __forceinline__ void ldsm4(uint32_t* r, uint32_t addr) {
    asm volatile("ldmatrix.sync.aligned.m8n8.x4.shared.b16 {%0,%1,%2,%3}, [%4];\n"
                 : "=r"(r[0]), "=r"(r[1]), "=r"(r[2]), "=r"(r[3]) : "r"(addr));
}
__device__ __forceinline__ void mma16816(float* c, const uint32_t* a,
                                         uint32_t b0, uint32_t b1) {
    asm volatile(
        "mma.sync.aligned.m16n8k16.row.col.f32.bf16.bf16.f32 "
        "{%0,%1,%2,%3}, {%4,%5,%6,%7}, {%8,%9}, {%0,%1,%2,%3};\n"
        : "+f"(c[0]), "+f"(c[1]), "+f"(c[2]), "+f"(c[3])
        : "r"(a[0]), "r"(a[1]), "r"(a[2]), "r"(a[3]), "r"(b0), "r"(b1));
}
__device__ __forceinline__ void mma16816h(uint32_t* c, const uint32_t* a,
                                          uint32_t b0, uint32_t b1) {
    asm volatile(
        "mma.sync.aligned.m16n8k16.row.col.f16.f16.f16.f16 "
        "{%0,%1}, {%2,%3,%4,%5}, {%6,%7}, {%0,%1};\n"
        : "+r"(c[0]), "+r"(c[1])
        : "r"(a[0]), "r"(a[1]), "r"(a[2]), "r"(a[3]), "r"(b0), "r"(b1));
}
__device__ __forceinline__ uint32_t pack_bf16x2(float lo, float hi) {
    __nv_bfloat162 h = __float22bfloat162_rn(make_float2(lo, hi));
    uint32_t u;
    memcpy(&u, &h, 4);
    return u;
}
__device__ __forceinline__ uint32_t pack_half2(float lo, float hi) {
    __half2 h = __float22half2_rn(make_float2(lo, hi));
    uint32_t u;
    memcpy(&u, &h, 4);
    return u;
}
__device__ __forceinline__ float2 unpack_bf16x2(uint32_t u) {
    __nv_bfloat162 h;
    memcpy(&h, &u, 4);
    return __bfloat1622float2(h);
}
__device__ __forceinline__ float2 unpack_half2(uint32_t u) {
    __half2 h;
    memcpy(&h, &u, 4);
    return __half22float2(h);
}

// ===========================================================================
// K-major SS GEMM (bf16, fp32 acc): D[i,j] = sum_k A[i,k]*B[j,k] + epilogue
// CTA 128x128, 4 warps (2x2), warp tile 64x64, K-chunks of 64, 3-stage
// cp.async pipeline (R9 ordering).
//   MODE 1: bf16 out + bias[j]
//   MODE 2: fp16 out + bias[i]      (V projection)
//   MODE 4: bf16 out (plain)
// ===========================================================================
#define NSTG 3
#define SMEMB (NSTG * 32768)

template<int MODE>
__global__ void __launch_bounds__(128, 2)
mma_gemm(const bf16* __restrict__ Ag, const bf16* __restrict__ Bg,
         const float* __restrict__ bias,
         void* __restrict__ Dg, int Ktot, int lda, int ldb, int ldd,
         size_t sA, size_t sB, size_t sD)
{
    extern __shared__ char smem[];
    const uint32_t s0 = smem_u32(smem);

    const int tid = threadIdx.x, warp = tid >> 5, lane = tid & 31;
    const int bz = blockIdx.z;
    const int i0 = blockIdx.y * 128, j0 = blockIdx.x * 128;
    const bf16* Ab = Ag + sA * bz;
    const bf16* Bb = Bg + sB * bz;

    const int wm = (warp >> 1) * 64;
    const int wn = (warp & 1) * 64;

    const int rAl = lane & 15;
    const int aHalf = lane >> 4;
    const int rBl = (lane & 7) + ((lane & 16) >> 1);
    const int bHalf = (lane >> 3) & 1;

    float acc[4][8][4];
    #pragma unroll
    for (int mi = 0; mi < 4; mi++)
        #pragma unroll
        for (int ni = 0; ni < 8; ni++)
            #pragma unroll
            for (int e = 0; e < 4; e++) acc[mi][ni][e] = 0.0f;

    auto load_stage = [&](int t) {
        const uint32_t base = s0 + (uint32_t)(t % NSTG) * 32768u;
        const int k0 = t * 64;
        #pragma unroll
        for (int it = 0; it < 16; it++) {
            int q = it * 128 + tid;
            int qq = q & 1023;
            int row = qq >> 3, c = qq & 7;
            uint32_t dst = base + (q < 1024 ? 0u : 16384u)
                         + (uint32_t)(row * 128 + ((c ^ (row & 7)) << 4));
            const bf16* src = (q < 1024)
                ? Ab + (size_t)(i0 + row) * lda + k0 + c * 8
                : Bb + (size_t)(j0 + row) * ldb + k0 + c * 8;
            cp_async16(dst, src);
        }
        cp_commit();
    };

    const int T = Ktot >> 6;
    load_stage(0);
    if (T > 1) load_stage(1); else cp_commit();

    for (int t = 0; t < T; t++) {
        if (t + 2 < T) load_stage(t + 2); else cp_commit();
        cp_wait<2>();
        __syncthreads();

        const uint32_t sa = s0 + (uint32_t)(t % NSTG) * 32768u;
        const uint32_t sb = sa + 16384u;
        #pragma unroll
        for (int k16 = 0; k16 < 4; k16++) {
            uint32_t a[4][4], b[4][4];
            #pragma unroll
            for (int mi = 0; mi < 4; mi++) {
                int row = wm + mi * 16 + rAl;
                int ch = 2 * k16 + aHalf;
                ldsm4(a[mi], sa + (uint32_t)(row * 128 + ((ch ^ (row & 7)) << 4)));
            }
            #pragma unroll
            for (int nh = 0; nh < 4; nh++) {
                int row = wn + nh * 16 + rBl;
                int ch = 2 * k16 + bHalf;
                ldsm4(b[nh], sb + (uint32_t)(row * 128 + ((ch ^ (row & 7)) << 4)));
            }
            #pragma unroll
            for (int mi = 0; mi < 4; mi++)
                #pragma unroll
                for (int ni = 0; ni < 8; ni++)
                    mma16816(acc[mi][ni], a[mi],
                             b[ni >> 1][(ni & 1) * 2], b[ni >> 1][(ni & 1) * 2 + 1]);
        }
        __syncthreads();
    }

    // ---- Epilogue ----
    const int er = lane >> 2;
    const int ec = 2 * (lane & 3);
    #pragma unroll
    for (int mi = 0; mi < 4; mi++)
        #pragma unroll
        for (int ni = 0; ni < 8; ni++) {
            const float* a4 = acc[mi][ni];
            int gm = i0 + wm + mi * 16 + er;
            int gn = j0 + wn + ni * 8 + ec;
            if (MODE == 4) {
                bf16* D = (bf16*)Dg + sD * bz;
                *(__nv_bfloat162*)&D[(size_t)gm * ldd + gn] =
                    __float22bfloat162_rn(make_float2(a4[0], a4[1]));
                *(__nv_bfloat162*)&D[(size_t)(gm + 8) * ldd + gn] =
                    __float22bfloat162_rn(make_float2(a4[2], a4[3]));
            } else if (MODE == 2) {
                __half* D = (__half*)Dg + sD * bz;
                float bb0 = bias[gm], bb1 = bias[gm + 8];
                *(__half2*)&D[(size_t)gm * ldd + gn] =
                    __float22half2_rn(make_float2(a4[0] + bb0, a4[1] + bb0));
                *(__half2*)&D[(size_t)(gm + 8) * ldd + gn] =
                    __float22half2_rn(make_float2(a4[2] + bb1, a4[3] + bb1));
            } else {                                    // MODE 1: bias over j
                bf16* D = (bf16*)Dg + sD * bz;
                float b0 = bias[gn], b1 = bias[gn + 1];
                *(__nv_bfloat162*)&D[(size_t)gm * ldd + gn] =
                    __float22bfloat162_rn(make_float2(a4[0] + b0, a4[1] + b1));
                *(__nv_bfloat162*)&D[(size_t)(gm + 8) * ldd + gn] =
                    __float22bfloat162_rn(make_float2(a4[2] + b0, a4[3] + b1));
            }
        }
}

// ===========================================================================
// AV GEMM (fp16 inputs, f16 acc + chunked fp32 promotion):
// out[i][j] = res[i][j] + sum_k V[i,k] * P[j,k],  K = 2048 fixed.
// Same tiling/pipeline as mma_gemm. Promote f16->f32 every 2 stages (128 K).
// ===========================================================================
__global__ void __launch_bounds__(128, 2)
av_gemm(const __half* __restrict__ Ag, const __half* __restrict__ Bg,
        const float* __restrict__ res, float* __restrict__ Dg,
        size_t sA, size_t sB, size_t sD, size_t sRes)
{
    extern __shared__ char smem[];
    const uint32_t s0 = smem_u32(smem);

    const int tid = threadIdx.x, warp = tid >> 5, lane = tid & 31;
    const int bz = blockIdx.z;
    const int i0 = blockIdx.y * 128, j0 = blockIdx.x * 128;
    const __half* Ab = Ag + sA * bz;
    const __half* Bb = Bg + sB * bz;

    const int wm = (warp >> 1) * 64;
    const int wn = (warp & 1) * 64;

    const int rAl = lane & 15;
    const int aHalf = lane >> 4;
    const int rBl = (lane & 7) + ((lane & 16) >> 1);
    const int bHalf = (lane >> 3) & 1;

    float accf[4][8][4];
    uint32_t acc16[4][8][2];
    #pragma unroll
    for (int mi = 0; mi < 4; mi++)
        #pragma unroll
        for (int ni = 0; ni < 8; ni++) {
            #pragma unroll
            for (int e = 0; e < 4; e++) accf[mi][ni][e] = 0.0f;
            acc16[mi][ni][0] = 0u; acc16[mi][ni][1] = 0u;
        }

    auto load_stage = [&](int t) {
        const uint32_t base = s0 + (uint32_t)(t % NSTG) * 32768u;
        const int k0 = t * 64;
        #pragma unroll
        for (int it = 0; it < 16; it++) {
            int q = it * 128 + tid;
            int qq = q & 1023;
            int row = qq >> 3, c = qq & 7;
            uint32_t dst = base + (q < 1024 ? 0u : 16384u)
                         + (uint32_t)(row * 128 + ((c ^ (row & 7)) << 4));
            const __half* src = (q < 1024)
                ? Ab + (size_t)(i0 + row) * N_ + k0 + c * 8
                : Bb + (size_t)(j0 + row) * N_ + k0 + c * 8;
            cp_async16(dst, src);
        }
        cp_commit();
    };

    const int T = N_ >> 6;   // 32
    load_stage(0);
    load_stage(1);

    for (int t = 0; t < T; t++) {
        if (t + 2 < T) load_stage(t + 2); else cp_commit();
        cp_wait<2>();
        __syncthreads();

        const uint32_t sa = s0 + (uint32_t)(t % NSTG) * 32768u;
        const uint32_t sb = sa + 16384u;
        #pragma unroll
        for (int k16 = 0; k16 < 4; k16++) {
            uint32_t a[4][4], b[4][4];
            #pragma unroll
            for (int mi = 0; mi < 4; mi++) {
                int row = wm + mi * 16 + rAl;
                int ch = 2 * k16 + aHalf;
                ldsm4(a[mi], sa + (uint32_t)(row * 128 + ((ch ^ (row & 7)) << 4)));
            }
            #pragma unroll
            for (int nh = 0; nh < 4; nh++) {
                int row = wn + nh * 16 + rBl;
                int ch = 2 * k16 + bHalf;
                ldsm4(b[nh], sb + (uint32_t)(row * 128 + ((ch ^ (row & 7)) << 4)));
            }
            #pragma unroll
            for (int mi = 0; mi < 4; mi++)
                #pragma unroll
                for (int ni = 0; ni < 8; ni++)
                    mma16816h(acc16[mi][ni], a[mi],
                              b[ni >> 1][(ni & 1) * 2], b[ni >> 1][(ni & 1) * 2 + 1]);
        }
        __syncthreads();

        // ---- promote f16 partials to fp32 every 2 stages (128 K-elems) ----
        if ((t & 1) || t == T - 1) {
            #pragma unroll
            for (int mi = 0; mi < 4; mi++)
                #pragma unroll
                for (int ni = 0; ni < 8; ni++) {
                    float2 lo = unpack_half2(acc16[mi][ni][0]);
                    float2 hi = unpack_half2(acc16[mi][ni][1]);
                    accf[mi][ni][0] += lo.x; accf[mi][ni][1] += lo.y;
                    accf[mi][ni][2] += hi.x; accf[mi][ni][3] += hi.y;
                    acc16[mi][ni][0] = 0u; acc16[mi][ni][1] = 0u;
                }
        }
    }

    // ---- Epilogue: residual + fp32 out ----
    const int er = lane >> 2;
    const int ec = 2 * (lane & 3);
    float* D = Dg + sD * bz;
    const float* R = res + sRes * bz;
    #pragma unroll
    for (int mi = 0; mi < 4; mi++)
        #pragma unroll
        for (int ni = 0; ni < 8; ni++) {
            const float* a4 = accf[mi][ni];
            int gm = i0 + wm + mi * 16 + er;
            int gn = j0 + wn + ni * 8 + ec;
            float2 r0 = *(const float2*)&R[(size_t)gm * N_ + gn];
            float2 r1 = *(const float2*)&R[(size_t)(gm + 8) * N_ + gn];
            *(float2*)&D[(size_t)gm * N_ + gn] = make_float2(r0.x + a4[0], r0.y + a4[1]);
            *(float2*)&D[(size_t)(gm + 8) * N_ + gn] = make_float2(r1.x + a4[2], r1.y + a4[3]);
        }
}

// ===========================================================================
// Fused prep: weight conversions + bias pack + x transpose, one launch.
// ===========================================================================
__global__ void __launch_bounds__(256)
prep_all(const float* __restrict__ Wq, const float* __restrict__ Wk,
         const float* __restrict__ Wv, const float* __restrict__ bq,
         const float* __restrict__ bk, const float* __restrict__ x)
{
    __shared__ float tile[32][33];
    const int b = blockIdx.x;
    const int tid = threadIdx.x;

    if (b < 512) {
        const float4* src;
        __nv_bfloat162* dst;
        int idx;
        if (b < 128) {
            src = (const float4*)Wq; dst = (__nv_bfloat162*)g_Wqk;
            idx = b * 256 + tid;
        } else if (b < 256) {
            src = (const float4*)Wk; dst = (__nv_bfloat162*)(g_Wqk + CH_ * C_);
            idx = (b - 128) * 256 + tid;
        } else {
            src = (const float4*)Wv; dst = (__nv_bfloat162*)g_Wv;
            idx = (b - 256) * 256 + tid;
        }
        float4 v = src[idx];
        dst[2 * idx]     = __float22bfloat162_rn(make_float2(v.x, v.y));
        dst[2 * idx + 1] = __float22bfloat162_rn(make_float2(v.z, v.w));
        if (b >= 256) {
            int idx2 = idx + 256 * 128;
            float4 v2 = ((const float4*)Wv)[idx2];
            dst[2 * idx2]     = __float22bfloat162_rn(make_float2(v2.x, v2.y));
            dst[2 * idx2 + 1] = __float22bfloat162_rn(make_float2(v2.z, v2.w));
        }
    } else if (b == 512) {
        g_bqk[tid]        = bq[tid];
        g_bqk[tid + CH_]  = bk[tid];
    } else {
        int t = b - 513;
        int bx = t & 63;
        int by = (t >> 6) & 15;
        int bz = t >> 10;
        const int c0 = by * 32, n0 = bx * 32;
        const float* xb = x + (size_t)bz * C_ * N_;
        bf16* xtb = g_xt + (size_t)bz * N_ * C_;
        const int tx = tid & 31, ty = tid >> 5;
        #pragma unroll
        for (int i = 0; i < 4; i++)
            tile[ty + 8 * i][tx] = xb[(size_t)(c0 + ty + 8 * i) * N_ + n0 + tx];
        __syncthreads();
        #pragma unroll
        for (int i = 0; i < 4; i++)
            xtb[(size_t)(n0 + ty + 8 * i) * C_ + c0 + tx] =
                __float2bfloat16(tile[tx][ty + 8 * i]);
    }
}

// ===========================================================================
// Softmax over last dim (2048). bf16 in (x1/16 at load), fp16 out.
// ===========================================================================
__global__ void __launch_bounds__(256)
softmax_kernel(const bf16* __restrict__ S, __half* __restrict__ P)
{
    const uint4* row = (const uint4*)(S + (size_t)blockIdx.x * N_);
    uint4* prow = (uint4*)(P + (size_t)blockIdx.x * N_);
    const int tid = threadIdx.x;

    uint4 u = row[tid];
    float v[8];
    {
        float2 f;
        f = unpack_bf16x2(u.x); v[0] = f.x * 0.0625f; v[1] = f.y * 0.0625f;
        f = unpack_bf16x2(u.y); v[2] = f.x * 0.0625f; v[3] = f.y * 0.0625f;
        f = unpack_bf16x2(u.z); v[4] = f.x * 0.0625f; v[5] = f.y * 0.0625f;
        f = unpack_bf16x2(u.w); v[6] = f.x * 0.0625f; v[7] = f.y * 0.0625f;
    }
    float mx = v[0];
    #pragma unroll
    for (int i = 1; i < 8; i++) mx = fmaxf(mx, v[i]);
    #pragma unroll
    for (int o = 16; o; o >>= 1) mx = fmaxf(mx, __shfl_xor_sync(0xFFFFFFFFu, mx, o));
    __shared__ float smax[8], ssum[8];
    if ((tid & 31) == 0) smax[tid >> 5] = mx;
    __syncthreads();
    mx = smax[0];
    #pragma unroll
    for (int w = 1; w < 8; w++) mx = fmaxf(mx, smax[w]);

    float sum = 0.0f;
    #pragma unroll
    for (int i = 0; i < 8; i++) { v[i] = __expf(v[i] - mx); sum += v[i]; }
    #pragma unroll
    for (int o = 16; o; o >>= 1) sum += __shfl_xor_sync(0xFFFFFFFFu, sum, o);
    if ((tid & 31) == 0) ssum[tid >> 5] = sum;
    __syncthreads();
    sum = ssum[0];
    #pragma unroll
    for (int w = 1; w < 8; w++) sum += ssum[w];

    float inv = 1.0f / sum;
    uint4 o4;
    o4.x = pack_half2(v[0] * inv, v[1] * inv);
    o4.y = pack_half2(v[2] * inv, v[3] * inv);
    o4.z = pack_half2(v[4] * inv, v[5] * inv);
    o4.w = pack_half2(v[6] * inv, v[7] * inv);
    prow[tid] = o4;
}

// ===========================================================================
extern "C" void kernel_launch(void* const* d_in, const int* in_sizes, int n_in,
                              void* d_out, int out_size)
{
    const float* x  = (const float*)d_in[0];
    const float* Wq = (const float*)d_in[1];
    const float* bq = (const float*)d_in[2];
    const float* Wk = (const float*)d_in[3];
    const float* bk = (const float*)d_in[4];
    const float* Wv = (const float*)d_in[5];
    const float* bv = (const float*)d_in[6];
    float* out = (float*)d_out;

    bf16 *xt, *Wqk, *Wvb, *QK, *Sp;
    __half *Vp, *Pp;
    float *bqk;
    cudaGetSymbolAddress((void**)&xt,  g_xt);
    cudaGetSymbolAddress((void**)&Wqk, g_Wqk);
    cudaGetSymbolAddress((void**)&Wvb, g_Wv);
    cudaGetSymbolAddress((void**)&bqk, g_bqk);
    cudaGetSymbolAddress((void**)&QK,  g_QK);
    cudaGetSymbolAddress((void**)&Vp,  g_V);
    cudaGetSymbolAddress((void**)&Sp,  g_S);
    cudaGetSymbolAddress((void**)&Pp,  g_P);

    cudaFuncSetAttribute(mma_gemm<1>, cudaFuncAttributeMaxDynamicSharedMemorySize, SMEMB);
    cudaFuncSetAttribute(mma_gemm<2>, cudaFuncAttributeMaxDynamicSharedMemorySize, SMEMB);
    cudaFuncSetAttribute(mma_gemm<4>, cudaFuncAttributeMaxDynamicSharedMemorySize, SMEMB);
    cudaFuncSetAttribute(av_gemm,     cudaFuncAttributeMaxDynamicSharedMemorySize, SMEMB);

    prep_all<<<513 + 8192, 256>>>(Wq, Wk, Wv, bq, bk, x);

    const size_t sXT = (size_t)N_ * C_;
    const size_t sQK = (size_t)N_ * C_;
    const size_t sX  = (size_t)C_ * N_;
    const size_t sS  = (size_t)N_ * N_;

    // QK[n][o] = sum_c xt[n,c] Wqk[o,c] + bqk[o]   (bf16 out)
    mma_gemm<1><<<dim3(C_ / 128, N_ / 128, B_), 128, SMEMB>>>(
        xt, Wqk, bqk, QK, C_, C_, C_, C_, sXT, 0, sQK);
    // V[c][m] = sum_k Wv[c,k] xt[m,k] + bv[c]      (fp16 out)
    mma_gemm<2><<<dim3(N_ / 128, C_ / 128, B_), 128, SMEMB>>>(
        Wvb, xt, bv, Vp, C_, C_, C_, N_, 0, sXT, sX);
    // S[n][m] = sum_c Q[n,c] K[m,c]                (unscaled, bf16 out)
    mma_gemm<4><<<dim3(N_ / 128, N_ / 128, B_), 128, SMEMB>>>(
        QK, QK + CH_, nullptr, Sp, CH_, C_, C_, N_, sQK, sQK, sS);
    // softmax (1/16 at load, fp16 out)
    softmax_kernel<<<B_ * N_, 256>>>(Sp, Pp);
    // out[c][n] = x[c][n] + sum_m V[c,m] P[n,m]    (f16 acc + fp32 promote)
    av_gemm<<<dim3(N_ / 128, C_ / 128, B_), 128, SMEMB>>>(
        Vp, Pp, x, out, sX, sS, sX, sX);
}

// round 14
// speedup vs baseline: 1.1012x; 1.1012x over previous
#include <cuda_runtime.h>
#include <cuda_bf16.h>
#include <cstdint>
#include <string.h>
#include <math.h>

typedef __nv_bfloat16 bf16;

#define B_ 8
#define C_ 512
#define N_ 2048
#define CH_ 256

// ---- device-global scratch ----
__device__ bf16   g_xt [B_ * N_ * C_];             // [n][c] bf16
__device__ bf16   g_Wqk[2 * CH_ * C_];             // rows 0-255 Wq, 256-511 Wk
__device__ bf16   g_Wv [C_ * C_];
__device__ float  g_bqk[2 * CH_];                  // packed bq|bk
__device__ bf16   g_QK [B_ * N_ * C_];             // [n][0..255]=Q, [256..511]=K
__device__ bf16   g_V  [B_ * C_ * N_];             // [c][m]
__device__ bf16   g_S  [(size_t)B_ * N_ * N_];     // [n][m] unscaled logits
__device__ bf16   g_P  [(size_t)B_ * N_ * N_];     // [n][m] probs

// ===========================================================================
// PTX helpers
// ===========================================================================
__device__ __forceinline__ uint32_t smem_u32(const void* p) {
    uint32_t a;
    asm("{ .reg .u64 t; cvta.to.shared.u64 t, %1; cvt.u32.u64 %0, t; }"
        : "=r"(a) : "l"(p));
    return a;
}
__device__ __forceinline__ void cp_async16(uint32_t dst, const void* src) {
    asm volatile("cp.async.cg.shared.global [%0], [%1], 16;\n" :: "r"(dst), "l"(src));
}
__device__ __forceinline__ void cp_commit() {
    asm volatile("cp.async.commit_group;\n");
}
template<int NW> __device__ __forceinline__ void cp_wait() {
    asm volatile("cp.async.wait_group %0;\n" :: "n"(NW));
}
__device__ __forceinline__ void ldsm4(uint32_t* r, uint32_t addr) {
    asm volatile("ldmatrix.sync.aligned.m8n8.x4.shared.b16 {%0,%1,%2,%3}, [%4];\n"
                 : "=r"(r[0]), "=r"(r[1]), "=r"(r[2]), "=r"(r[3]) : "r"(addr));
}
__device__ __forceinline__ void mma16816(float* c, const uint32_t* a,
                                         uint32_t b0, uint32_t b1) {
    asm volatile(
        "mma.sync.aligned.m16n8k16.row.col.f32.bf16.bf16.f32 "
        "{%0,%1,%2,%3}, {%4,%5,%6,%7}, {%8,%9}, {%0,%1,%2,%3};\n"
        : "+f"(c[0]), "+f"(c[1]), "+f"(c[2]), "+f"(c[3])
        : "r"(a[0]), "r"(a[1]), "r"(a[2]), "r"(a[3]), "r"(b0), "r"(b1));
}
__device__ __forceinline__ uint32_t pack_bf16x2(float lo, float hi) {
    __nv_bfloat162 h = __float22bfloat162_rn(make_float2(lo, hi));
    uint32_t u;
    memcpy(&u, &h, 4);
    return u;
}
__device__ __forceinline__ float2 unpack_bf16x2(uint32_t u) {
    __nv_bfloat162 h;
    memcpy(&h, &u, 4);
    return __bfloat1622float2(h);
}

#define NSTG 3
#define SMEMB (NSTG * 32768)

// ===========================================================================
// K-major SS GEMM (bf16, fp32 acc): D[i,j] = sum_k A[i,k]*B[j,k] + epilogue
// CTA 128x128, 4 warps (2x2), warp tile 64x64, K-chunks of 64, 3-stage
// cp.async pipeline.
//   MODE 3: fp32 out + res[i][j]   (AV + residual)
//   MODE 4: bf16 out (plain)       (scores)
// ===========================================================================
template<int MODE>
__global__ void __launch_bounds__(128, 2)
mma_gemm(const bf16* __restrict__ Ag, const bf16* __restrict__ Bg,
         const float* __restrict__ res,
         void* __restrict__ Dg, int Ktot, int lda, int ldb, int ldd,
         size_t sA, size_t sB, size_t sD, size_t sRes)
{
    extern __shared__ char smem[];
    const uint32_t s0 = smem_u32(smem);

    const int tid = threadIdx.x, warp = tid >> 5, lane = tid & 31;
    const int bz = blockIdx.z;
    const int i0 = blockIdx.y * 128, j0 = blockIdx.x * 128;
    const bf16* Ab = Ag + sA * bz;
    const bf16* Bb = Bg + sB * bz;

    const int wm = (warp >> 1) * 64;
    const int wn = (warp & 1) * 64;

    const int rAl = lane & 15;
    const int aHalf = lane >> 4;
    const int rBl = (lane & 7) + ((lane & 16) >> 1);
    const int bHalf = (lane >> 3) & 1;

    float acc[4][8][4];
    #pragma unroll
    for (int mi = 0; mi < 4; mi++)
        #pragma unroll
        for (int ni = 0; ni < 8; ni++)
            #pragma unroll
            for (int e = 0; e < 4; e++) acc[mi][ni][e] = 0.0f;

    auto load_stage = [&](int t) {
        const uint32_t base = s0 + (uint32_t)(t % NSTG) * 32768u;
        const int k0 = t * 64;
        #pragma unroll
        for (int it = 0; it < 16; it++) {
            int q = it * 128 + tid;
            int qq = q & 1023;
            int row = qq >> 3, c = qq & 7;
            uint32_t dst = base + (q < 1024 ? 0u : 16384u)
                         + (uint32_t)(row * 128 + ((c ^ (row & 7)) << 4));
            const bf16* src = (q < 1024)
                ? Ab + (size_t)(i0 + row) * lda + k0 + c * 8
                : Bb + (size_t)(j0 + row) * ldb + k0 + c * 8;
            cp_async16(dst, src);
        }
        cp_commit();
    };

    const int T = Ktot >> 6;
    load_stage(0);
    if (T > 1) load_stage(1); else cp_commit();

    for (int t = 0; t < T; t++) {
        if (t + 2 < T) load_stage(t + 2); else cp_commit();
        cp_wait<2>();
        __syncthreads();

        const uint32_t sa = s0 + (uint32_t)(t % NSTG) * 32768u;
        const uint32_t sb = sa + 16384u;
        #pragma unroll
        for (int k16 = 0; k16 < 4; k16++) {
            uint32_t a[4][4], b[4][4];
            #pragma unroll
            for (int mi = 0; mi < 4; mi++) {
                int row = wm + mi * 16 + rAl;
                int ch = 2 * k16 + aHalf;
                ldsm4(a[mi], sa + (uint32_t)(row * 128 + ((ch ^ (row & 7)) << 4)));
            }
            #pragma unroll
            for (int nh = 0; nh < 4; nh++) {
                int row = wn + nh * 16 + rBl;
                int ch = 2 * k16 + bHalf;
                ldsm4(b[nh], sb + (uint32_t)(row * 128 + ((ch ^ (row & 7)) << 4)));
            }
            #pragma unroll
            for (int mi = 0; mi < 4; mi++)
                #pragma unroll
                for (int ni = 0; ni < 8; ni++)
                    mma16816(acc[mi][ni], a[mi],
                             b[ni >> 1][(ni & 1) * 2], b[ni >> 1][(ni & 1) * 2 + 1]);
        }
        __syncthreads();
    }

    // ---- Epilogue ----
    const int er = lane >> 2;
    const int ec = 2 * (lane & 3);
    #pragma unroll
    for (int mi = 0; mi < 4; mi++)
        #pragma unroll
        for (int ni = 0; ni < 8; ni++) {
            const float* a4 = acc[mi][ni];
            int gm = i0 + wm + mi * 16 + er;
            int gn = j0 + wn + ni * 8 + ec;
            if (MODE == 3) {
                float* D = (float*)Dg + sD * bz;
                const float* R = res + sRes * bz;
                float2 r0 = *(const float2*)&R[(size_t)gm * ldd + gn];
                float2 r1 = *(const float2*)&R[(size_t)(gm + 8) * ldd + gn];
                *(float2*)&D[(size_t)gm * ldd + gn] =
                    make_float2(r0.x + a4[0], r0.y + a4[1]);
                *(float2*)&D[(size_t)(gm + 8) * ldd + gn] =
                    make_float2(r1.x + a4[2], r1.y + a4[3]);
            } else {
                bf16* D = (bf16*)Dg + sD * bz;
                *(__nv_bfloat162*)&D[(size_t)gm * ldd + gn] =
                    __float22bfloat162_rn(make_float2(a4[0], a4[1]));
                *(__nv_bfloat162*)&D[(size_t)(gm + 8) * ldd + gn] =
                    __float22bfloat162_rn(make_float2(a4[2], a4[3]));
            }
        }
}

// ===========================================================================
// Merged QK + V projection, one launch. Grid (128, 1, 8).
//   blockIdx.x < 64 : QK[n][o] = sum_c xt[n,c] Wqk[o,c] + bqk[o]  (bias-j)
//                     iy = t>>2 (16 n-blocks), jx = t&3 (4 o-blocks)
//   blockIdx.x >= 64: V[c][m]  = sum_k Wv[c,k] xt[m,k] + bv[c]    (bias-i)
//                     iy = t>>4 (4 c-blocks), jx = t&15 (16 m-blocks)
// K = 512 for both. Same mainloop as mma_gemm.
// ===========================================================================
__global__ void __launch_bounds__(128, 2)
proj_gemm(const float* __restrict__ bv)
{
    extern __shared__ char smem[];
    const uint32_t s0 = smem_u32(smem);

    const int tid = threadIdx.x, warp = tid >> 5, lane = tid & 31;
    const int bz = blockIdx.z;
    const int tcta = blockIdx.x;
    const bool isV = tcta >= 64;

    int i0, j0, lda, ldb, ldd;
    const bf16 *Ab, *Bb;
    const size_t sXT = (size_t)N_ * C_;
    if (!isV) {
        i0 = (tcta >> 2) * 128; j0 = (tcta & 3) * 128;
        Ab = g_xt + sXT * bz; lda = C_;
        Bb = g_Wqk;           ldb = C_;
        ldd = C_;
    } else {
        int t = tcta - 64;
        i0 = (t >> 4) * 128; j0 = (t & 15) * 128;
        Ab = g_Wv;            lda = C_;
        Bb = g_xt + sXT * bz; ldb = C_;
        ldd = N_;
    }

    const int wm = (warp >> 1) * 64;
    const int wn = (warp & 1) * 64;
    const int rAl = lane & 15;
    const int aHalf = lane >> 4;
    const int rBl = (lane & 7) + ((lane & 16) >> 1);
    const int bHalf = (lane >> 3) & 1;

    float acc[4][8][4];
    #pragma unroll
    for (int mi = 0; mi < 4; mi++)
        #pragma unroll
        for (int ni = 0; ni < 8; ni++)
            #pragma unroll
            for (int e = 0; e < 4; e++) acc[mi][ni][e] = 0.0f;

    auto load_stage = [&](int t) {
        const uint32_t base = s0 + (uint32_t)(t % NSTG) * 32768u;
        const int k0 = t * 64;
        #pragma unroll
        for (int it = 0; it < 16; it++) {
            int q = it * 128 + tid;
            int qq = q & 1023;
            int row = qq >> 3, c = qq & 7;
            uint32_t dst = base + (q < 1024 ? 0u : 16384u)
                         + (uint32_t)(row * 128 + ((c ^ (row & 7)) << 4));
            const bf16* src = (q < 1024)
                ? Ab + (size_t)(i0 + row) * lda + k0 + c * 8
                : Bb + (size_t)(j0 + row) * ldb + k0 + c * 8;
            cp_async16(dst, src);
        }
        cp_commit();
    };

    const int T = C_ >> 6;   // 8
    load_stage(0);
    load_stage(1);

    for (int t = 0; t < T; t++) {
        if (t + 2 < T) load_stage(t + 2); else cp_commit();
        cp_wait<2>();
        __syncthreads();

        const uint32_t sa = s0 + (uint32_t)(t % NSTG) * 32768u;
        const uint32_t sb = sa + 16384u;
        #pragma unroll
        for (int k16 = 0; k16 < 4; k16++) {
            uint32_t a[4][4], b[4][4];
            #pragma unroll
            for (int mi = 0; mi < 4; mi++) {
                int row = wm + mi * 16 + rAl;
                int ch = 2 * k16 + aHalf;
                ldsm4(a[mi], sa + (uint32_t)(row * 128 + ((ch ^ (row & 7)) << 4)));
            }
            #pragma unroll
            for (int nh = 0; nh < 4; nh++) {
                int row = wn + nh * 16 + rBl;
                int ch = 2 * k16 + bHalf;
                ldsm4(b[nh], sb + (uint32_t)(row * 128 + ((ch ^ (row & 7)) << 4)));
            }
            #pragma unroll
            for (int mi = 0; mi < 4; mi++)
                #pragma unroll
                for (int ni = 0; ni < 8; ni++)
                    mma16816(acc[mi][ni], a[mi],
                             b[ni >> 1][(ni & 1) * 2], b[ni >> 1][(ni & 1) * 2 + 1]);
        }
        __syncthreads();
    }

    // ---- Epilogue ----
    const int er = lane >> 2;
    const int ec = 2 * (lane & 3);
    #pragma unroll
    for (int mi = 0; mi < 4; mi++)
        #pragma unroll
        for (int ni = 0; ni < 8; ni++) {
            const float* a4 = acc[mi][ni];
            int gm = i0 + wm + mi * 16 + er;
            int gn = j0 + wn + ni * 8 + ec;
            if (!isV) {
                bf16* D = g_QK + (size_t)N_ * C_ * bz;
                float b0 = g_bqk[gn], b1 = g_bqk[gn + 1];
                *(__nv_bfloat162*)&D[(size_t)gm * ldd + gn] =
                    __float22bfloat162_rn(make_float2(a4[0] + b0, a4[1] + b1));
                *(__nv_bfloat162*)&D[(size_t)(gm + 8) * ldd + gn] =
                    __float22bfloat162_rn(make_float2(a4[2] + b0, a4[3] + b1));
            } else {
                bf16* D = g_V + (size_t)C_ * N_ * bz;
                float bb0 = bv[gm], bb1 = bv[gm + 8];
                *(__nv_bfloat162*)&D[(size_t)gm * ldd + gn] =
                    __float22bfloat162_rn(make_float2(a4[0] + bb0, a4[1] + bb0));
                *(__nv_bfloat162*)&D[(size_t)(gm + 8) * ldd + gn] =
                    __float22bfloat162_rn(make_float2(a4[2] + bb1, a4[3] + bb1));
            }
        }
}

// ===========================================================================
// Fused prep: weight conversions + bias pack + x transpose, one launch.
// ===========================================================================
__global__ void __launch_bounds__(256)
prep_all(const float* __restrict__ Wq, const float* __restrict__ Wk,
         const float* __restrict__ Wv, const float* __restrict__ bq,
         const float* __restrict__ bk, const float* __restrict__ x)
{
    __shared__ float tile[32][33];
    const int b = blockIdx.x;
    const int tid = threadIdx.x;

    if (b < 512) {
        const float4* src;
        __nv_bfloat162* dst;
        int idx;
        if (b < 128) {
            src = (const float4*)Wq; dst = (__nv_bfloat162*)g_Wqk;
            idx = b * 256 + tid;
        } else if (b < 256) {
            src = (const float4*)Wk; dst = (__nv_bfloat162*)(g_Wqk + CH_ * C_);
            idx = (b - 128) * 256 + tid;
        } else {
            src = (const float4*)Wv; dst = (__nv_bfloat162*)g_Wv;
            idx = (b - 256) * 256 + tid;
        }
        float4 v = src[idx];
        dst[2 * idx]     = __float22bfloat162_rn(make_float2(v.x, v.y));
        dst[2 * idx + 1] = __float22bfloat162_rn(make_float2(v.z, v.w));
        if (b >= 256) {
            int idx2 = idx + 256 * 128;
            float4 v2 = ((const float4*)Wv)[idx2];
            dst[2 * idx2]     = __float22bfloat162_rn(make_float2(v2.x, v2.y));
            dst[2 * idx2 + 1] = __float22bfloat162_rn(make_float2(v2.z, v2.w));
        }
    } else if (b == 512) {
        g_bqk[tid]        = bq[tid];
        g_bqk[tid + CH_]  = bk[tid];
    } else {
        int t = b - 513;
        int bx = t & 63;
        int by = (t >> 6) & 15;
        int bz = t >> 10;
        const int c0 = by * 32, n0 = bx * 32;
        const float* xb = x + (size_t)bz * C_ * N_;
        bf16* xtb = g_xt + (size_t)bz * N_ * C_;
        const int tx = tid & 31, ty = tid >> 5;
        #pragma unroll
        for (int i = 0; i < 4; i++)
            tile[ty + 8 * i][tx] = xb[(size_t)(c0 + ty + 8 * i) * N_ + n0 + tx];
        __syncthreads();
        #pragma unroll
        for (int i = 0; i < 4; i++)
            xtb[(size_t)(n0 + ty + 8 * i) * C_ + c0 + tx] =
                __float2bfloat16(tile[tx][ty + 8 * i]);
    }
}

// ===========================================================================
// Softmax over last dim (2048). bf16 in (x1/16 at load), bf16 out.
// ===========================================================================
__global__ void __launch_bounds__(256)
softmax_kernel(const bf16* __restrict__ S, bf16* __restrict__ P)
{
    const uint4* row = (const uint4*)(S + (size_t)blockIdx.x * N_);
    uint4* prow = (uint4*)(P + (size_t)blockIdx.x * N_);
    const int tid = threadIdx.x;

    uint4 u = row[tid];
    float v[8];
    {
        float2 f;
        f = unpack_bf16x2(u.x); v[0] = f.x * 0.0625f; v[1] = f.y * 0.0625f;
        f = unpack_bf16x2(u.y); v[2] = f.x * 0.0625f; v[3] = f.y * 0.0625f;
        f = unpack_bf16x2(u.z); v[4] = f.x * 0.0625f; v[5] = f.y * 0.0625f;
        f = unpack_bf16x2(u.w); v[6] = f.x * 0.0625f; v[7] = f.y * 0.0625f;
    }
    float mx = v[0];
    #pragma unroll
    for (int i = 1; i < 8; i++) mx = fmaxf(mx, v[i]);
    #pragma unroll
    for (int o = 16; o; o >>= 1) mx = fmaxf(mx, __shfl_xor_sync(0xFFFFFFFFu, mx, o));
    __shared__ float smax[8], ssum[8];
    if ((tid & 31) == 0) smax[tid >> 5] = mx;
    __syncthreads();
    mx = smax[0];
    #pragma unroll
    for (int w = 1; w < 8; w++) mx = fmaxf(mx, smax[w]);

    float sum = 0.0f;
    #pragma unroll
    for (int i = 0; i < 8; i++) { v[i] = __expf(v[i] - mx); sum += v[i]; }
    #pragma unroll
    for (int o = 16; o; o >>= 1) sum += __shfl_xor_sync(0xFFFFFFFFu, sum, o);
    if ((tid & 31) == 0) ssum[tid >> 5] = sum;
    __syncthreads();
    sum = ssum[0];
    #pragma unroll
    for (int w = 1; w < 8; w++) sum += ssum[w];

    float inv = 1.0f / sum;
    uint4 o4;
    o4.x = pack_bf16x2(v[0] * inv, v[1] * inv);
    o4.y = pack_bf16x2(v[2] * inv, v[3] * inv);
    o4.z = pack_bf16x2(v[4] * inv, v[5] * inv);
    o4.w = pack_bf16x2(v[6] * inv, v[7] * inv);
    prow[tid] = o4;
}

// ===========================================================================
extern "C" void kernel_launch(void* const* d_in, const int* in_sizes, int n_in,
                              void* d_out, int out_size)
{
    const float* x  = (const float*)d_in[0];
    const float* Wq = (const float*)d_in[1];
    const float* bq = (const float*)d_in[2];
    const float* Wk = (const float*)d_in[3];
    const float* bk = (const float*)d_in[4];
    const float* Wv = (const float*)d_in[5];
    const float* bv = (const float*)d_in[6];
    float* out = (float*)d_out;

    bf16 *QK, *Vp, *Sp, *Pp;
    cudaGetSymbolAddress((void**)&QK,  g_QK);
    cudaGetSymbolAddress((void**)&Vp,  g_V);
    cudaGetSymbolAddress((void**)&Sp,  g_S);
    cudaGetSymbolAddress((void**)&Pp,  g_P);

    cudaFuncSetAttribute(mma_gemm<3>, cudaFuncAttributeMaxDynamicSharedMemorySize, SMEMB);
    cudaFuncSetAttribute(mma_gemm<4>, cudaFuncAttributeMaxDynamicSharedMemorySize, SMEMB);
    cudaFuncSetAttribute(proj_gemm,   cudaFuncAttributeMaxDynamicSharedMemorySize, SMEMB);

    // fused prep (weights cvt + bias pack + x transpose)
    prep_all<<<513 + 8192, 256>>>(Wq, Wk, Wv, bq, bk, x);

    const size_t sQK = (size_t)N_ * C_;
    const size_t sX  = (size_t)C_ * N_;
    const size_t sS  = (size_t)N_ * N_;

    // merged QK + V projections (one launch, 1024 CTAs)
    proj_gemm<<<dim3(128, 1, B_), 128, SMEMB>>>(bv);

    // S[n][m] = sum_c Q[n,c] K[m,c]   (unscaled, bf16 out)
    mma_gemm<4><<<dim3(N_ / 128, N_ / 128, B_), 128, SMEMB>>>(
        QK, QK + CH_, nullptr, Sp, CH_, C_, C_, N_, sQK, sQK, sS, 0);
    // softmax (1/16 at load)
    softmax_kernel<<<B_ * N_, 256>>>(Sp, Pp);
    // out[c][n] = x[c][n] + sum_m V[c,m] P[n,m]
    mma_gemm<3><<<dim3(N_ / 128, C_ / 128, B_), 128, SMEMB>>>(
        Vp, Pp, x, out, N_, N_, N_, N_, sX, sS, sX, sX);
}

// round 15
// speedup vs baseline: 1.1926x; 1.0830x over previous
#include <cuda_runtime.h>
#include <cuda_bf16.h>
#include <cstdint>
#include <string.h>
#include <math.h>

typedef __nv_bfloat16 bf16;

#define B_ 8
#define C_ 512
#define N_ 2048
#define CH_ 256

// ---- device-global scratch ----
__device__ bf16   g_xt [B_ * N_ * C_];             // [n][c] bf16
__device__ bf16   g_Wqk[2 * CH_ * C_];             // rows 0-255 Wq, 256-511 Wk
__device__ bf16   g_Wv [C_ * C_];
__device__ float  g_bqk[2 * CH_];                  // packed bq|bk
__device__ bf16   g_QK [B_ * N_ * C_];             // [n][0..255]=Q, [256..511]=K
__device__ bf16   g_V  [B_ * C_ * N_];             // [c][m]
__device__ bf16   g_E  [(size_t)B_ * N_ * N_];     // [n][m] exp(logit), unnormalized
__device__ float  g_rowsum[B_ * N_];               // per-row exp sums

// ===========================================================================
// PTX helpers
// ===========================================================================
__device__ __forceinline__ uint32_t smem_u32(const void* p) {
    uint32_t a;
    asm("{ .reg .u64 t; cvta.to.shared.u64 t, %1; cvt.u32.u64 %0, t; }"
        : "=r"(a) : "l"(p));
    return a;
}
__device__ __forceinline__ void cp_async16(uint32_t dst, const void* src) {
    asm volatile("cp.async.cg.shared.global [%0], [%1], 16;\n" :: "r"(dst), "l"(src));
}
__device__ __forceinline__ void cp_commit() {
    asm volatile("cp.async.commit_group;\n");
}
template<int NW> __device__ __forceinline__ void cp_wait() {
    asm volatile("cp.async.wait_group %0;\n" :: "n"(NW));
}
__device__ __forceinline__ void ldsm4(uint32_t* r, uint32_t addr) {
    asm volatile("ldmatrix.sync.aligned.m8n8.x4.shared.b16 {%0,%1,%2,%3}, [%4];\n"
                 : "=r"(r[0]), "=r"(r[1]), "=r"(r[2]), "=r"(r[3]) : "r"(addr));
}
__device__ __forceinline__ void mma16816(float* c, const uint32_t* a,
                                         uint32_t b0, uint32_t b1) {
    asm volatile(
        "mma.sync.aligned.m16n8k16.row.col.f32.bf16.bf16.f32 "
        "{%0,%1,%2,%3}, {%4,%5,%6,%7}, {%8,%9}, {%0,%1,%2,%3};\n"
        : "+f"(c[0]), "+f"(c[1]), "+f"(c[2]), "+f"(c[3])
        : "r"(a[0]), "r"(a[1]), "r"(a[2]), "r"(a[3]), "r"(b0), "r"(b1));
}

#define NSTG 3
#define SMEMB (NSTG * 32768)

// ===========================================================================
// K-major SS GEMM (bf16, fp32 acc): D[i,j] = sum_k A[i,k]*B[j,k] + epilogue
// CTA 128x128, 4 warps (2x2), warp tile 64x64, K-chunks of 64, 3-stage
// cp.async pipeline.
//   MODE 3: fp32 out, acc * (1/rowsum[j]) + res[i][j]    (AV + residual)
//   MODE 5: bf16 out = exp(acc/16), atomicAdd row sums   (scores+exp)
// ===========================================================================
template<int MODE>
__global__ void __launch_bounds__(128, 2)
mma_gemm(const bf16* __restrict__ Ag, const bf16* __restrict__ Bg,
         const float* __restrict__ res, float* __restrict__ rowsum,
         void* __restrict__ Dg, int Ktot, int lda, int ldb, int ldd,
         size_t sA, size_t sB, size_t sD, size_t sRes)
{
    extern __shared__ char smem[];
    const uint32_t s0 = smem_u32(smem);

    const int tid = threadIdx.x, warp = tid >> 5, lane = tid & 31;
    const int bz = blockIdx.z;
    const int i0 = blockIdx.y * 128, j0 = blockIdx.x * 128;
    const bf16* Ab = Ag + sA * bz;
    const bf16* Bb = Bg + sB * bz;

    const int wm = (warp >> 1) * 64;
    const int wn = (warp & 1) * 64;

    const int rAl = lane & 15;
    const int aHalf = lane >> 4;
    const int rBl = (lane & 7) + ((lane & 16) >> 1);
    const int bHalf = (lane >> 3) & 1;

    float acc[4][8][4];
    #pragma unroll
    for (int mi = 0; mi < 4; mi++)
        #pragma unroll
        for (int ni = 0; ni < 8; ni++)
            #pragma unroll
            for (int e = 0; e < 4; e++) acc[mi][ni][e] = 0.0f;

    auto load_stage = [&](int t) {
        const uint32_t base = s0 + (uint32_t)(t % NSTG) * 32768u;
        const int k0 = t * 64;
        #pragma unroll
        for (int it = 0; it < 16; it++) {
            int q = it * 128 + tid;
            int qq = q & 1023;
            int row = qq >> 3, c = qq & 7;
            uint32_t dst = base + (q < 1024 ? 0u : 16384u)
                         + (uint32_t)(row * 128 + ((c ^ (row & 7)) << 4));
            const bf16* src = (q < 1024)
                ? Ab + (size_t)(i0 + row) * lda + k0 + c * 8
                : Bb + (size_t)(j0 + row) * ldb + k0 + c * 8;
            cp_async16(dst, src);
        }
        cp_commit();
    };

    const int T = Ktot >> 6;
    load_stage(0);
    if (T > 1) load_stage(1); else cp_commit();

    for (int t = 0; t < T; t++) {
        if (t + 2 < T) load_stage(t + 2); else cp_commit();
        cp_wait<2>();
        __syncthreads();

        const uint32_t sa = s0 + (uint32_t)(t % NSTG) * 32768u;
        const uint32_t sb = sa + 16384u;
        #pragma unroll
        for (int k16 = 0; k16 < 4; k16++) {
            uint32_t a[4][4], b[4][4];
            #pragma unroll
            for (int mi = 0; mi < 4; mi++) {
                int row = wm + mi * 16 + rAl;
                int ch = 2 * k16 + aHalf;
                ldsm4(a[mi], sa + (uint32_t)(row * 128 + ((ch ^ (row & 7)) << 4)));
            }
            #pragma unroll
            for (int nh = 0; nh < 4; nh++) {
                int row = wn + nh * 16 + rBl;
                int ch = 2 * k16 + bHalf;
                ldsm4(b[nh], sb + (uint32_t)(row * 128 + ((ch ^ (row & 7)) << 4)));
            }
            #pragma unroll
            for (int mi = 0; mi < 4; mi++)
                #pragma unroll
                for (int ni = 0; ni < 8; ni++)
                    mma16816(acc[mi][ni], a[mi],
                             b[ni >> 1][(ni & 1) * 2], b[ni >> 1][(ni & 1) * 2 + 1]);
        }
        __syncthreads();
    }

    // ---- Epilogue ----
    const int er = lane >> 2;
    const int ec = 2 * (lane & 3);

    if (MODE == 5) {
        // scores: E = exp(acc/16) -> bf16, plus per-row sum atomics
        bf16* D = (bf16*)Dg + sD * bz;
        float* rsb = rowsum + (size_t)bz * N_;
        #pragma unroll
        for (int mi = 0; mi < 4; mi++) {
            float rs0 = 0.0f, rs1 = 0.0f;
            int gm = i0 + wm + mi * 16 + er;
            #pragma unroll
            for (int ni = 0; ni < 8; ni++) {
                const float* a4 = acc[mi][ni];
                int gn = j0 + wn + ni * 8 + ec;
                float e00 = __expf(a4[0] * 0.0625f);
                float e01 = __expf(a4[1] * 0.0625f);
                float e10 = __expf(a4[2] * 0.0625f);
                float e11 = __expf(a4[3] * 0.0625f);
                *(__nv_bfloat162*)&D[(size_t)gm * ldd + gn] =
                    __float22bfloat162_rn(make_float2(e00, e01));
                *(__nv_bfloat162*)&D[(size_t)(gm + 8) * ldd + gn] =
                    __float22bfloat162_rn(make_float2(e10, e11));
                rs0 += e00 + e01;
                rs1 += e10 + e11;
            }
            // reduce across the 4 lanes sharing this row (lane&3)
            rs0 += __shfl_xor_sync(0xFFFFFFFFu, rs0, 1);
            rs0 += __shfl_xor_sync(0xFFFFFFFFu, rs0, 2);
            rs1 += __shfl_xor_sync(0xFFFFFFFFu, rs1, 1);
            rs1 += __shfl_xor_sync(0xFFFFFFFFu, rs1, 2);
            if ((lane & 3) == 0) {
                atomicAdd(&rsb[gm], rs0);
                atomicAdd(&rsb[gm + 8], rs1);
            }
        }
    } else {
        // AV: out = res + acc / rowsum[j]
        float* D = (float*)Dg + sD * bz;
        const float* R = res + sRes * bz;
        const float* rsb = rowsum + (size_t)bz * N_;
        float inv[8][2];
        #pragma unroll
        for (int ni = 0; ni < 8; ni++) {
            int gn = j0 + wn + ni * 8 + ec;
            inv[ni][0] = 1.0f / rsb[gn];
            inv[ni][1] = 1.0f / rsb[gn + 1];
        }
        #pragma unroll
        for (int mi = 0; mi < 4; mi++)
            #pragma unroll
            for (int ni = 0; ni < 8; ni++) {
                const float* a4 = acc[mi][ni];
                int gm = i0 + wm + mi * 16 + er;
                int gn = j0 + wn + ni * 8 + ec;
                float2 r0 = *(const float2*)&R[(size_t)gm * ldd + gn];
                float2 r1 = *(const float2*)&R[(size_t)(gm + 8) * ldd + gn];
                *(float2*)&D[(size_t)gm * ldd + gn] =
                    make_float2(r0.x + a4[0] * inv[ni][0], r0.y + a4[1] * inv[ni][1]);
                *(float2*)&D[(size_t)(gm + 8) * ldd + gn] =
                    make_float2(r1.x + a4[2] * inv[ni][0], r1.y + a4[3] * inv[ni][1]);
            }
    }
}

// ===========================================================================
// Merged QK + V projection, one launch. Grid (128, 1, 8).
//   blockIdx.x < 64 : QK[n][o] = sum_c xt[n,c] Wqk[o,c] + bqk[o]  (bias-j)
//   blockIdx.x >= 64: V[c][m]  = sum_k Wv[c,k] xt[m,k] + bv[c]    (bias-i)
// ===========================================================================
__global__ void __launch_bounds__(128, 2)
proj_gemm(const float* __restrict__ bv)
{
    extern __shared__ char smem[];
    const uint32_t s0 = smem_u32(smem);

    const int tid = threadIdx.x, warp = tid >> 5, lane = tid & 31;
    const int bz = blockIdx.z;
    const int tcta = blockIdx.x;
    const bool isV = tcta >= 64;

    int i0, j0, lda, ldb, ldd;
    const bf16 *Ab, *Bb;
    const size_t sXT = (size_t)N_ * C_;
    if (!isV) {
        i0 = (tcta >> 2) * 128; j0 = (tcta & 3) * 128;
        Ab = g_xt + sXT * bz; lda = C_;
        Bb = g_Wqk;           ldb = C_;
        ldd = C_;
    } else {
        int t = tcta - 64;
        i0 = (t >> 4) * 128; j0 = (t & 15) * 128;
        Ab = g_Wv;            lda = C_;
        Bb = g_xt + sXT * bz; ldb = C_;
        ldd = N_;
    }

    const int wm = (warp >> 1) * 64;
    const int wn = (warp & 1) * 64;
    const int rAl = lane & 15;
    const int aHalf = lane >> 4;
    const int rBl = (lane & 7) + ((lane & 16) >> 1);
    const int bHalf = (lane >> 3) & 1;

    float acc[4][8][4];
    #pragma unroll
    for (int mi = 0; mi < 4; mi++)
        #pragma unroll
        for (int ni = 0; ni < 8; ni++)
            #pragma unroll
            for (int e = 0; e < 4; e++) acc[mi][ni][e] = 0.0f;

    auto load_stage = [&](int t) {
        const uint32_t base = s0 + (uint32_t)(t % NSTG) * 32768u;
        const int k0 = t * 64;
        #pragma unroll
        for (int it = 0; it < 16; it++) {
            int q = it * 128 + tid;
            int qq = q & 1023;
            int row = qq >> 3, c = qq & 7;
            uint32_t dst = base + (q < 1024 ? 0u : 16384u)
                         + (uint32_t)(row * 128 + ((c ^ (row & 7)) << 4));
            const bf16* src = (q < 1024)
                ? Ab + (size_t)(i0 + row) * lda + k0 + c * 8
                : Bb + (size_t)(j0 + row) * ldb + k0 + c * 8;
            cp_async16(dst, src);
        }
        cp_commit();
    };

    const int T = C_ >> 6;   // 8
    load_stage(0);
    load_stage(1);

    for (int t = 0; t < T; t++) {
        if (t + 2 < T) load_stage(t + 2); else cp_commit();
        cp_wait<2>();
        __syncthreads();

        const uint32_t sa = s0 + (uint32_t)(t % NSTG) * 32768u;
        const uint32_t sb = sa + 16384u;
        #pragma unroll
        for (int k16 = 0; k16 < 4; k16++) {
            uint32_t a[4][4], b[4][4];
            #pragma unroll
            for (int mi = 0; mi < 4; mi++) {
                int row = wm + mi * 16 + rAl;
                int ch = 2 * k16 + aHalf;
                ldsm4(a[mi], sa + (uint32_t)(row * 128 + ((ch ^ (row & 7)) << 4)));
            }
            #pragma unroll
            for (int nh = 0; nh < 4; nh++) {
                int row = wn + nh * 16 + rBl;
                int ch = 2 * k16 + bHalf;
                ldsm4(b[nh], sb + (uint32_t)(row * 128 + ((ch ^ (row & 7)) << 4)));
            }
            #pragma unroll
            for (int mi = 0; mi < 4; mi++)
                #pragma unroll
                for (int ni = 0; ni < 8; ni++)
                    mma16816(acc[mi][ni], a[mi],
                             b[ni >> 1][(ni & 1) * 2], b[ni >> 1][(ni & 1) * 2 + 1]);
        }
        __syncthreads();
    }

    // ---- Epilogue ----
    const int er = lane >> 2;
    const int ec = 2 * (lane & 3);
    #pragma unroll
    for (int mi = 0; mi < 4; mi++)
        #pragma unroll
        for (int ni = 0; ni < 8; ni++) {
            const float* a4 = acc[mi][ni];
            int gm = i0 + wm + mi * 16 + er;
            int gn = j0 + wn + ni * 8 + ec;
            if (!isV) {
                bf16* D = g_QK + (size_t)N_ * C_ * bz;
                float b0 = g_bqk[gn], b1 = g_bqk[gn + 1];
                *(__nv_bfloat162*)&D[(size_t)gm * ldd + gn] =
                    __float22bfloat162_rn(make_float2(a4[0] + b0, a4[1] + b1));
                *(__nv_bfloat162*)&D[(size_t)(gm + 8) * ldd + gn] =
                    __float22bfloat162_rn(make_float2(a4[2] + b0, a4[3] + b1));
            } else {
                bf16* D = g_V + (size_t)C_ * N_ * bz;
                float bb0 = bv[gm], bb1 = bv[gm + 8];
                *(__nv_bfloat162*)&D[(size_t)gm * ldd + gn] =
                    __float22bfloat162_rn(make_float2(a4[0] + bb0, a4[1] + bb0));
                *(__nv_bfloat162*)&D[(size_t)(gm + 8) * ldd + gn] =
                    __float22bfloat162_rn(make_float2(a4[2] + bb1, a4[3] + bb1));
            }
        }
}

// ===========================================================================
// Fused prep: weight conversions + bias pack + rowsum zero + x transpose.
// ===========================================================================
__global__ void __launch_bounds__(256)
prep_all(const float* __restrict__ Wq, const float* __restrict__ Wk,
         const float* __restrict__ Wv, const float* __restrict__ bq,
         const float* __restrict__ bk, const float* __restrict__ x)
{
    __shared__ float tile[32][33];
    const int b = blockIdx.x;
    const int tid = threadIdx.x;

    if (b < 512) {
        const float4* src;
        __nv_bfloat162* dst;
        int idx;
        if (b < 128) {
            src = (const float4*)Wq; dst = (__nv_bfloat162*)g_Wqk;
            idx = b * 256 + tid;
        } else if (b < 256) {
            src = (const float4*)Wk; dst = (__nv_bfloat162*)(g_Wqk + CH_ * C_);
            idx = (b - 128) * 256 + tid;
        } else {
            src = (const float4*)Wv; dst = (__nv_bfloat162*)g_Wv;
            idx = (b - 256) * 256 + tid;
        }
        float4 v = src[idx];
        dst[2 * idx]     = __float22bfloat162_rn(make_float2(v.x, v.y));
        dst[2 * idx + 1] = __float22bfloat162_rn(make_float2(v.z, v.w));
        if (b >= 256) {
            int idx2 = idx + 256 * 128;
            float4 v2 = ((const float4*)Wv)[idx2];
            dst[2 * idx2]     = __float22bfloat162_rn(make_float2(v2.x, v2.y));
            dst[2 * idx2 + 1] = __float22bfloat162_rn(make_float2(v2.z, v2.w));
        }
    } else if (b == 512) {
        g_bqk[tid]        = bq[tid];
        g_bqk[tid + CH_]  = bk[tid];
        #pragma unroll
        for (int i = 0; i < 64; i++)
            g_rowsum[tid + i * 256] = 0.0f;
    } else {
        int t = b - 513;
        int bx = t & 63;
        int by = (t >> 6) & 15;
        int bz = t >> 10;
        const int c0 = by * 32, n0 = bx * 32;
        const float* xb = x + (size_t)bz * C_ * N_;
        bf16* xtb = g_xt + (size_t)bz * N_ * C_;
        const int tx = tid & 31, ty = tid >> 5;
        #pragma unroll
        for (int i = 0; i < 4; i++)
            tile[ty + 8 * i][tx] = xb[(size_t)(c0 + ty + 8 * i) * N_ + n0 + tx];
        __syncthreads();
        #pragma unroll
        for (int i = 0; i < 4; i++)
            xtb[(size_t)(n0 + ty + 8 * i) * C_ + c0 + tx] =
                __float2bfloat16(tile[tx][ty + 8 * i]);
    }
}

// ===========================================================================
extern "C" void kernel_launch(void* const* d_in, const int* in_sizes, int n_in,
                              void* d_out, int out_size)
{
    const float* x  = (const float*)d_in[0];
    const float* Wq = (const float*)d_in[1];
    const float* bq = (const float*)d_in[2];
    const float* Wk = (const float*)d_in[3];
    const float* bk = (const float*)d_in[4];
    const float* Wv = (const float*)d_in[5];
    const float* bv = (const float*)d_in[6];
    float* out = (float*)d_out;

    bf16 *QK, *Vp, *Ep;
    float* rsum;
    cudaGetSymbolAddress((void**)&QK,   g_QK);
    cudaGetSymbolAddress((void**)&Vp,   g_V);
    cudaGetSymbolAddress((void**)&Ep,   g_E);
    cudaGetSymbolAddress((void**)&rsum, g_rowsum);

    cudaFuncSetAttribute(mma_gemm<3>, cudaFuncAttributeMaxDynamicSharedMemorySize, SMEMB);
    cudaFuncSetAttribute(mma_gemm<5>, cudaFuncAttributeMaxDynamicSharedMemorySize, SMEMB);
    cudaFuncSetAttribute(proj_gemm,   cudaFuncAttributeMaxDynamicSharedMemorySize, SMEMB);

    // fused prep (weights cvt + bias pack + rowsum zero + x transpose)
    prep_all<<<513 + 8192, 256>>>(Wq, Wk, Wv, bq, bk, x);

    const size_t sQK = (size_t)N_ * C_;
    const size_t sX  = (size_t)C_ * N_;
    const size_t sS  = (size_t)N_ * N_;

    // merged QK + V projections (one launch, 1024 CTAs)
    proj_gemm<<<dim3(128, 1, B_), 128, SMEMB>>>(bv);

    // E[n][m] = exp((Q.K)/16), row sums via atomics
    mma_gemm<5><<<dim3(N_ / 128, N_ / 128, B_), 128, SMEMB>>>(
        QK, QK + CH_, nullptr, rsum, Ep, CH_, C_, C_, N_, sQK, sQK, sS, 0);

    // out[c][n] = x[c][n] + (sum_m V[c,m] E[n,m]) / rowsum[n]
    mma_gemm<3><<<dim3(N_ / 128, C_ / 128, B_), 128, SMEMB>>>(
        Vp, Ep, x, rsum, out, N_, N_, N_, N_, sX, sS, sX, sX);
}

// round 16
// speedup vs baseline: 1.2304x; 1.0317x over previous
#include <cuda_runtime.h>
#include <cuda_bf16.h>
#include <cstdint>
#include <string.h>
#include <math.h>

typedef __nv_bfloat16 bf16;

#define B_ 8
#define C_ 512
#define N_ 2048
#define CH_ 256

// ---- device-global scratch ----
__device__ bf16     g_xt [B_ * N_ * C_];             // [n][c] bf16
__device__ bf16     g_Wqk[2 * CH_ * C_];             // rows 0-255 Wq, 256-511 Wk
__device__ bf16     g_Wv [C_ * C_];
__device__ float    g_bqk[2 * CH_];                  // packed bq|bk
__device__ bf16     g_QK [B_ * N_ * C_];             // [n][0..255]=Q, [256..511]=K
__device__ bf16     g_V  [B_ * C_ * N_];             // [c][m]
__device__ bf16     g_E  [(size_t)B_ * N_ * N_];     // [n][m] exp(logit)
__device__ float    g_rowsum[B_ * N_];               // per-row exp sums
__device__ unsigned g_cntQK[B_ * 16];                // proj QK done per (b, n-block)
__device__ unsigned g_cntV [B_ * 4];                 // proj V done per (b, c-block)
__device__ unsigned g_cntS [B_ * 16];                // scores done per (b, n-block)

// ===========================================================================
// PTX helpers
// ===========================================================================
__device__ __forceinline__ uint32_t smem_u32(const void* p) {
    uint32_t a;
    asm("{ .reg .u64 t; cvta.to.shared.u64 t, %1; cvt.u32.u64 %0, t; }"
        : "=r"(a) : "l"(p));
    return a;
}
__device__ __forceinline__ void cp_async16(uint32_t dst, const void* src) {
    asm volatile("cp.async.cg.shared.global [%0], [%1], 16;\n" :: "r"(dst), "l"(src));
}
__device__ __forceinline__ void cp_commit() {
    asm volatile("cp.async.commit_group;\n");
}
template<int NW> __device__ __forceinline__ void cp_wait() {
    asm volatile("cp.async.wait_group %0;\n" :: "n"(NW));
}
__device__ __forceinline__ void ldsm4(uint32_t* r, uint32_t addr) {
    asm volatile("ldmatrix.sync.aligned.m8n8.x4.shared.b16 {%0,%1,%2,%3}, [%4];\n"
                 : "=r"(r[0]), "=r"(r[1]), "=r"(r[2]), "=r"(r[3]) : "r"(addr));
}
__device__ __forceinline__ void mma16816(float* c, const uint32_t* a,
                                         uint32_t b0, uint32_t b1) {
    asm volatile(
        "mma.sync.aligned.m16n8k16.row.col.f32.bf16.bf16.f32 "
        "{%0,%1,%2,%3}, {%4,%5,%6,%7}, {%8,%9}, {%0,%1,%2,%3};\n"
        : "+f"(c[0]), "+f"(c[1]), "+f"(c[2]), "+f"(c[3])
        : "r"(a[0]), "r"(a[1]), "r"(a[2]), "r"(a[3]), "r"(b0), "r"(b1));
}
__device__ __forceinline__ unsigned ld_acquire(const unsigned* p) {
    unsigned v;
    asm volatile("ld.acquire.gpu.u32 %0, [%1];" : "=r"(v) : "l"(p));
    return v;
}

#define NSTG 3
#define SMEMB (NSTG * 32768)

// ===========================================================================
// Shared 128x128 K-major mainloop: acc[i][j] += sum_k A[i0+i,k]*B[j0+j,k]
// ===========================================================================
__device__ __forceinline__ void gemm_main(
    const bf16* __restrict__ Ab, const bf16* __restrict__ Bb,
    int lda, int ldb, int i0, int j0, int T,
    uint32_t s0, int tid, int wm, int wn,
    int rAl, int aHalf, int rBl, int bHalf,
    float acc[4][8][4])
{
    auto load_stage = [&](int t) {
        const uint32_t base = s0 + (uint32_t)(t % NSTG) * 32768u;
        const int k0 = t * 64;
        #pragma unroll
        for (int it = 0; it < 16; it++) {
            int q = it * 128 + tid;
            int qq = q & 1023;
            int row = qq >> 3, c = qq & 7;
            uint32_t dst = base + (q < 1024 ? 0u : 16384u)
                         + (uint32_t)(row * 128 + ((c ^ (row & 7)) << 4));
            const bf16* src = (q < 1024)
                ? Ab + (size_t)(i0 + row) * lda + k0 + c * 8
                : Bb + (size_t)(j0 + row) * ldb + k0 + c * 8;
            cp_async16(dst, src);
        }
        cp_commit();
    };

    load_stage(0);
    if (T > 1) load_stage(1); else cp_commit();

    for (int t = 0; t < T; t++) {
        if (t + 2 < T) load_stage(t + 2); else cp_commit();
        cp_wait<2>();
        __syncthreads();

        const uint32_t sa = s0 + (uint32_t)(t % NSTG) * 32768u;
        const uint32_t sb = sa + 16384u;
        #pragma unroll
        for (int k16 = 0; k16 < 4; k16++) {
            uint32_t a[4][4], b[4][4];
            #pragma unroll
            for (int mi = 0; mi < 4; mi++) {
                int row = wm + mi * 16 + rAl;
                int ch = 2 * k16 + aHalf;
                ldsm4(a[mi], sa + (uint32_t)(row * 128 + ((ch ^ (row & 7)) << 4)));
            }
            #pragma unroll
            for (int nh = 0; nh < 4; nh++) {
                int row = wn + nh * 16 + rBl;
                int ch = 2 * k16 + bHalf;
                ldsm4(b[nh], sb + (uint32_t)(row * 128 + ((ch ^ (row & 7)) << 4)));
            }
            #pragma unroll
            for (int mi = 0; mi < 4; mi++)
                #pragma unroll
                for (int ni = 0; ni < 8; ni++)
                    mma16816(acc[mi][ni], a[mi],
                             b[ni >> 1][(ni & 1) * 2], b[ni >> 1][(ni & 1) * 2 + 1]);
        }
        __syncthreads();
    }
}

// ===========================================================================
// Fused proj + scores + AV megakernel. Grid = 3584 CTAs, in dependency order:
//   bid [0, 1024)    : projections (QK: bid&127 < 64, else V)
//   bid [1024, 3072) : scores + exp + rowsum atomics (gated on cntQK)
//   bid [3072, 3584) : AV + normalize + residual (gated on cntS, cntV)
// Dispatch is in bid order on sm_103a, so waiters' producers are always
// dispatched first -> no deadlock.
// ===========================================================================
__global__ void __launch_bounds__(128, 2)
megakernel(const float* __restrict__ x, const float* __restrict__ bv,
           float* __restrict__ out)
{
    extern __shared__ char smem[];
    const uint32_t s0 = smem_u32(smem);
    const int tid = threadIdx.x, warp = tid >> 5, lane = tid & 31;
    const int wm = (warp >> 1) * 64;
    const int wn = (warp & 1) * 64;
    const int rAl = lane & 15;
    const int aHalf = lane >> 4;
    const int rBl = (lane & 7) + ((lane & 16) >> 1);
    const int bHalf = (lane >> 3) & 1;
    const int er = lane >> 2;
    const int ec = 2 * (lane & 3);
    const int bid = blockIdx.x;

    float acc[4][8][4];
    #pragma unroll
    for (int mi = 0; mi < 4; mi++)
        #pragma unroll
        for (int ni = 0; ni < 8; ni++)
            #pragma unroll
            for (int e = 0; e < 4; e++) acc[mi][ni][e] = 0.0f;

    const size_t sXT = (size_t)N_ * C_;
    const size_t sX  = (size_t)C_ * N_;
    const size_t sS  = (size_t)N_ * N_;

    if (bid < 1024) {
        // ---------------- projections ----------------
        const int b = bid >> 7, t = bid & 127;
        const bool isV = t >= 64;
        int i0, j0, lda, ldb;
        const bf16 *Ab, *Bb;
        if (!isV) {
            i0 = (t >> 2) * 128; j0 = (t & 3) * 128;
            Ab = g_xt + sXT * b; lda = C_;
            Bb = g_Wqk;          ldb = C_;
        } else {
            int tt = t - 64;
            i0 = (tt >> 4) * 128; j0 = (tt & 15) * 128;
            Ab = g_Wv;           lda = C_;
            Bb = g_xt + sXT * b; ldb = C_;
        }
        gemm_main(Ab, Bb, lda, ldb, i0, j0, C_ >> 6, s0, tid,
                  wm, wn, rAl, aHalf, rBl, bHalf, acc);

        if (!isV) {
            bf16* D = g_QK + sXT * b;
            #pragma unroll
            for (int mi = 0; mi < 4; mi++)
                #pragma unroll
                for (int ni = 0; ni < 8; ni++) {
                    const float* a4 = acc[mi][ni];
                    int gm = i0 + wm + mi * 16 + er;
                    int gn = j0 + wn + ni * 8 + ec;
                    float b0 = g_bqk[gn], b1 = g_bqk[gn + 1];
                    *(__nv_bfloat162*)&D[(size_t)gm * C_ + gn] =
                        __float22bfloat162_rn(make_float2(a4[0] + b0, a4[1] + b1));
                    *(__nv_bfloat162*)&D[(size_t)(gm + 8) * C_ + gn] =
                        __float22bfloat162_rn(make_float2(a4[2] + b0, a4[3] + b1));
                }
            __syncthreads();
            __threadfence();
            if (tid == 0) atomicAdd(&g_cntQK[b * 16 + (t >> 2)], 1u);
        } else {
            bf16* D = g_V + sX * b;
            #pragma unroll
            for (int mi = 0; mi < 4; mi++)
                #pragma unroll
                for (int ni = 0; ni < 8; ni++) {
                    const float* a4 = acc[mi][ni];
                    int gm = i0 + wm + mi * 16 + er;
                    int gn = j0 + wn + ni * 8 + ec;
                    float bb0 = bv[gm], bb1 = bv[gm + 8];
                    *(__nv_bfloat162*)&D[(size_t)gm * N_ + gn] =
                        __float22bfloat162_rn(make_float2(a4[0] + bb0, a4[1] + bb0));
                    *(__nv_bfloat162*)&D[(size_t)(gm + 8) * N_ + gn] =
                        __float22bfloat162_rn(make_float2(a4[2] + bb1, a4[3] + bb1));
                }
            __syncthreads();
            __threadfence();
            if (tid == 0) atomicAdd(&g_cntV[b * 4 + ((t - 64) >> 4)], 1u);
        }
    } else if (bid < 3072) {
        // ---------------- scores + exp + rowsum ----------------
        const int s = bid - 1024;
        const int b = s >> 8, r = s & 255;
        const int ix = r & 15, iy = r >> 4;
        const int i0 = iy * 128, j0 = ix * 128;

        if (tid == 0) {
            while (ld_acquire(&g_cntQK[b * 16 + iy]) < 4u) __nanosleep(64);
            while (ld_acquire(&g_cntQK[b * 16 + ix]) < 4u) __nanosleep(64);
        }
        __syncthreads();

        gemm_main(g_QK + sXT * b, g_QK + sXT * b + CH_, C_, C_, i0, j0,
                  CH_ >> 6, s0, tid, wm, wn, rAl, aHalf, rBl, bHalf, acc);

        bf16* D = g_E + sS * b;
        float* rsb = g_rowsum + (size_t)b * N_;
        #pragma unroll
        for (int mi = 0; mi < 4; mi++) {
            float rs0 = 0.0f, rs1 = 0.0f;
            int gm = i0 + wm + mi * 16 + er;
            #pragma unroll
            for (int ni = 0; ni < 8; ni++) {
                const float* a4 = acc[mi][ni];
                int gn = j0 + wn + ni * 8 + ec;
                float e00 = __expf(a4[0] * 0.0625f);
                float e01 = __expf(a4[1] * 0.0625f);
                float e10 = __expf(a4[2] * 0.0625f);
                float e11 = __expf(a4[3] * 0.0625f);
                *(__nv_bfloat162*)&D[(size_t)gm * N_ + gn] =
                    __float22bfloat162_rn(make_float2(e00, e01));
                *(__nv_bfloat162*)&D[(size_t)(gm + 8) * N_ + gn] =
                    __float22bfloat162_rn(make_float2(e10, e11));
                rs0 += e00 + e01;
                rs1 += e10 + e11;
            }
            rs0 += __shfl_xor_sync(0xFFFFFFFFu, rs0, 1);
            rs0 += __shfl_xor_sync(0xFFFFFFFFu, rs0, 2);
            rs1 += __shfl_xor_sync(0xFFFFFFFFu, rs1, 1);
            rs1 += __shfl_xor_sync(0xFFFFFFFFu, rs1, 2);
            if ((lane & 3) == 0) {
                atomicAdd(&rsb[gm], rs0);
                atomicAdd(&rsb[gm + 8], rs1);
            }
        }
        __syncthreads();
        __threadfence();
        if (tid == 0) atomicAdd(&g_cntS[b * 16 + iy], 1u);
    } else {
        // ---------------- AV + normalize + residual ----------------
        const int s = bid - 3072;
        const int b = s >> 6, r = s & 63;
        const int jx = r & 15, cy = r >> 4;
        const int i0 = cy * 128, j0 = jx * 128;

        if (tid == 0) {
            while (ld_acquire(&g_cntS[b * 16 + jx]) < 16u) __nanosleep(64);
            while (ld_acquire(&g_cntV[b * 4 + cy]) < 16u) __nanosleep(64);
        }
        __syncthreads();

        gemm_main(g_V + sX * b, g_E + sS * b, N_, N_, i0, j0,
                  N_ >> 6, s0, tid, wm, wn, rAl, aHalf, rBl, bHalf, acc);

        float* D = out + sX * b;
        const float* R = x + sX * b;
        const float* rsb = g_rowsum + (size_t)b * N_;
        float inv[8][2];
        #pragma unroll
        for (int ni = 0; ni < 8; ni++) {
            int gn = j0 + wn + ni * 8 + ec;
            inv[ni][0] = 1.0f / rsb[gn];
            inv[ni][1] = 1.0f / rsb[gn + 1];
        }
        #pragma unroll
        for (int mi = 0; mi < 4; mi++)
            #pragma unroll
            for (int ni = 0; ni < 8; ni++) {
                const float* a4 = acc[mi][ni];
                int gm = i0 + wm + mi * 16 + er;
                int gn = j0 + wn + ni * 8 + ec;
                float2 r0 = *(const float2*)&R[(size_t)gm * N_ + gn];
                float2 r1 = *(const float2*)&R[(size_t)(gm + 8) * N_ + gn];
                *(float2*)&D[(size_t)gm * N_ + gn] =
                    make_float2(r0.x + a4[0] * inv[ni][0], r0.y + a4[1] * inv[ni][1]);
                *(float2*)&D[(size_t)(gm + 8) * N_ + gn] =
                    make_float2(r1.x + a4[2] * inv[ni][0], r1.y + a4[3] * inv[ni][1]);
            }
    }
}

// ===========================================================================
// Fused prep: weight cvt + bias pack + counters/rowsum zero + x transpose.
// ===========================================================================
__global__ void __launch_bounds__(256)
prep_all(const float* __restrict__ Wq, const float* __restrict__ Wk,
         const float* __restrict__ Wv, const float* __restrict__ bq,
         const float* __restrict__ bk, const float* __restrict__ x)
{
    __shared__ float tile[32][33];
    const int b = blockIdx.x;
    const int tid = threadIdx.x;

    if (b < 512) {
        const float4* src;
        __nv_bfloat162* dst;
        int idx;
        if (b < 128) {
            src = (const float4*)Wq; dst = (__nv_bfloat162*)g_Wqk;
            idx = b * 256 + tid;
        } else if (b < 256) {
            src = (const float4*)Wk; dst = (__nv_bfloat162*)(g_Wqk + CH_ * C_);
            idx = (b - 128) * 256 + tid;
        } else {
            src = (const float4*)Wv; dst = (__nv_bfloat162*)g_Wv;
            idx = (b - 256) * 256 + tid;
        }
        float4 v = src[idx];
        dst[2 * idx]     = __float22bfloat162_rn(make_float2(v.x, v.y));
        dst[2 * idx + 1] = __float22bfloat162_rn(make_float2(v.z, v.w));
        if (b >= 256) {
            int idx2 = idx + 256 * 128;
            float4 v2 = ((const float4*)Wv)[idx2];
            dst[2 * idx2]     = __float22bfloat162_rn(make_float2(v2.x, v2.y));
            dst[2 * idx2 + 1] = __float22bfloat162_rn(make_float2(v2.z, v2.w));
        }
    } else if (b == 512) {
        g_bqk[tid]        = bq[tid];
        g_bqk[tid + CH_]  = bk[tid];
        #pragma unroll
        for (int i = 0; i < 64; i++)
            g_rowsum[tid + i * 256] = 0.0f;
        if (tid < 128) g_cntQK[tid] = 0u;
        else if (tid < 160) g_cntV[tid - 128] = 0u;
        else if (tid < 288 - 0 && tid >= 160 && tid < 288) {
            // map 160..287 -> cntS[0..127]
            if (tid - 160 < 128) g_cntS[tid - 160] = 0u;
        }
    } else {
        int t = b - 513;
        int bx = t & 63;
        int by = (t >> 6) & 15;
        int bz = t >> 10;
        const int c0 = by * 32, n0 = bx * 32;
        const float* xb = x + (size_t)bz * C_ * N_;
        bf16* xtb = g_xt + (size_t)bz * N_ * C_;
        const int tx = tid & 31, ty = tid >> 5;
        #pragma unroll
        for (int i = 0; i < 4; i++)
            tile[ty + 8 * i][tx] = xb[(size_t)(c0 + ty + 8 * i) * N_ + n0 + tx];
        __syncthreads();
        #pragma unroll
        for (int i = 0; i < 4; i++)
            xtb[(size_t)(n0 + ty + 8 * i) * C_ + c0 + tx] =
                __float2bfloat16(tile[tx][ty + 8 * i]);
    }
}

// ===========================================================================
extern "C" void kernel_launch(void* const* d_in, const int* in_sizes, int n_in,
                              void* d_out, int out_size)
{
    const float* x  = (const float*)d_in[0];
    const float* Wq = (const float*)d_in[1];
    const float* bq = (const float*)d_in[2];
    const float* Wk = (const float*)d_in[3];
    const float* bk = (const float*)d_in[4];
    const float* Wv = (const float*)d_in[5];
    const float* bv = (const float*)d_in[6];
    float* out = (float*)d_out;

    cudaFuncSetAttribute(megakernel, cudaFuncAttributeMaxDynamicSharedMemorySize, SMEMB);

    // prep (weights cvt + bias pack + counters zero + x transpose)
    prep_all<<<513 + 8192, 256>>>(Wq, Wk, Wv, bq, bk, x);

    // fused proj -> scores -> AV, dependency-gated, single launch
    megakernel<<<3584, 128, SMEMB>>>(x, bv, out);
}